// round 14
// baseline (speedup 1.0000x reference)
#include <cuda_runtime.h>
#include <cstddef>

#define Bn 16
#define Nn 2048
#define Cn 128
#define NP 512
#define CIN 131
#define PROW 132
#define NROWS (3*Bn*NP)
#define NTILES 4096
#define NCTR   8192
#define NTASK  (NTILES + NCTR)
#define NWORK  768

__device__ float g_featT[Bn*Nn*Cn];
__device__ float g_pooled[NROWS*PROW];
__device__ volatile int g_prog[Bn];        // FPS progress per batch
__device__ int g_task = 0;                 // global ticket
__device__ volatile int g_tdone = 0;       // transpose tiles completed

// smem overlay (float offsets):
//  worker: W2p[0,4624)  (136 c-rows x 17 float2 pairs, tf32)
//          b2s[4624,4784) W1s[4784,5104) b1s[5104,5136)
//          Hs[5136,9232)  (8 warps x 512 = 16 rows x 32 k, tf32; tile alias)
//          relm[9232,9520) (masks 192 | rel_s 96*3)
//          idx[9520,9616) pooled[9616,10012) tno@10012
//  fps:    xs[0,2048) ys[2048,4096) zs[4096,6144) cand float4[2][8] @6144
#define W2P_OFF 0
#define B2_OFF  4624
#define W1_OFF  4784
#define B1_OFF  5104
#define HS_OFF  5136
#define RM_OFF  9232
#define IDX_OFF 9520
#define PL_OFF  9616
#define TNO_OFF 10012
#define SMEMF   10016

__device__ __forceinline__ float to_tf32(float x) {
    unsigned u;
    asm("cvt.rna.tf32.f32 %0, %1;" : "=r"(u) : "f"(x));
    return __uint_as_float(u);
}

#define MMA_TF32(d0,d1,d2,d3,a0,a1,a2,a3,b0,b1) \
  asm volatile("mma.sync.aligned.m16n8k8.row.col.f32.tf32.tf32.f32 " \
    "{%0,%1,%2,%3}, {%4,%5,%6,%7}, {%8,%9}, {%0,%1,%2,%3};" \
    : "+f"(d0), "+f"(d1), "+f"(d2), "+f"(d3) \
    : "r"(a0), "r"(a1), "r"(a2), "r"(a3), "r"(b0), "r"(b1))

__global__ __launch_bounds__(256) void k_main(const float* __restrict__ xyz,
                                              const float* __restrict__ feat,
                                              const float* __restrict__ W1,
                                              const float* __restrict__ b1,
                                              const float* __restrict__ W2,
                                              const float* __restrict__ b2,
                                              float* __restrict__ out_xyz) {
    __shared__ __align__(16) float smem_f[SMEMF];
    int tid = threadIdx.x, lane = tid & 31, w = tid >> 5;

    if (blockIdx.x < 16) {
        // ================= FPS (one block per batch, 8 pts/thread) =========
        float* xs = smem_f;
        float* ys = smem_f + 2048;
        float* zs = smem_f + 4096;
        float4* cand = (float4*)(smem_f + 6144);   // [2][8]
        int b = blockIdx.x;
        const float* src = xyz + (size_t)b * Nn * 3;
        for (int t = tid; t < Nn; t += 256) {
            xs[t] = src[t*3 + 0]; ys[t] = src[t*3 + 1]; zs[t] = src[t*3 + 2];
        }
        __syncthreads();
        float X[8], Y[8], Z[8], D[8];
#pragma unroll
        for (int q = 0; q < 8; ++q) {
            int i = tid*8 + q;
            X[q] = xs[i]; Y[q] = ys[i]; Z[q] = zs[i];
            D[q] = 1e10f;
        }
        float px = xs[0], py = ys[0], pz = zs[0];
        if (tid == 0) {
            out_xyz[(size_t)b*NP*3 + 0] = px;
            out_xyz[(size_t)b*NP*3 + 1] = py;
            out_xyz[(size_t)b*NP*3 + 2] = pz;
        }
        for (int it = 1; it < NP; ++it) {
#pragma unroll
            for (int q = 0; q < 8; ++q) {
                float ax = X[q] - px, ay = Y[q] - py, az = Z[q] - pz;
                float dd = __fadd_rn(__fadd_rn(__fmul_rn(ax,ax), __fmul_rn(ay,ay)),
                                     __fmul_rn(az,az));
                D[q] = fminf(D[q], dd);
            }
            float v0 = D[0], xa = X[0], ya = Y[0], za = Z[0];
            if (D[1] > v0) { v0 = D[1]; xa = X[1]; ya = Y[1]; za = Z[1]; }
            float v2 = D[2], xb = X[2], yb = Y[2], zb = Z[2];
            if (D[3] > v2) { v2 = D[3]; xb = X[3]; yb = Y[3]; zb = Z[3]; }
            float v4 = D[4], xc = X[4], yc = Y[4], zc = Z[4];
            if (D[5] > v4) { v4 = D[5]; xc = X[5]; yc = Y[5]; zc = Z[5]; }
            float v6 = D[6], xd = X[6], yd = Y[6], zd = Z[6];
            if (D[7] > v6) { v6 = D[7]; xd = X[7]; yd = Y[7]; zd = Z[7]; }
            if (v2 > v0) { v0 = v2; xa = xb; ya = yb; za = zb; }
            if (v6 > v4) { v4 = v6; xc = xd; yc = yd; zc = zd; }
            if (v4 > v0) { v0 = v4; xa = xc; ya = yc; za = zc; }
            unsigned bits = __float_as_uint(v0);
            unsigned m = __reduce_max_sync(0xffffffffu, bits);
            unsigned bal = __ballot_sync(0xffffffffu, bits == m);
            int srcl = __ffs(bal) - 1;
            float wx = __shfl_sync(0xffffffffu, xa, srcl);
            float wy = __shfl_sync(0xffffffffu, ya, srcl);
            float wz = __shfl_sync(0xffffffffu, za, srcl);
            int bufi = it & 1;
            if (lane == 0)
                cand[bufi*8 + w] = make_float4(__uint_as_float(m), wx, wy, wz);
            __syncthreads();
            float4 c = cand[bufi*8 + (lane & 7)];
            unsigned vv = __float_as_uint(c.x);
            unsigned m2 = __reduce_max_sync(0xffffffffu, vv);
            unsigned b2_ = __ballot_sync(0xffffffffu, vv == m2);
            int s2 = __ffs(b2_) - 1;
            px = __shfl_sync(0xffffffffu, c.y, s2);
            py = __shfl_sync(0xffffffffu, c.z, s2);
            pz = __shfl_sync(0xffffffffu, c.w, s2);
            if (tid == 0) {
                out_xyz[(size_t)(b*NP + it)*3 + 0] = px;
                out_xyz[(size_t)(b*NP + it)*3 + 1] = py;
                out_xyz[(size_t)(b*NP + it)*3 + 2] = pz;
                if ((it & 3) == 3 || it == NP-1) {
                    __threadfence();
                    g_prog[b] = it + 1;
                }
            }
        }
        return;
    }

    // ================= persistent worker ===================================
    float2* W2p   = (float2*)(smem_f + W2P_OFF);   // [c][17] pairs (b0,b1)
    float* b2s    = smem_f + B2_OFF;
    float* W1s    = smem_f + W1_OFF;
    float* b1s    = smem_f + B1_OFF;
    float* Hs     = smem_f + HS_OFF;     // per-warp 512 floats; tile alias
    unsigned* masks = (unsigned*)(smem_f + RM_OFF);
    float* rel_s  = smem_f + RM_OFF;     // [96][3], alias of masks
    int*  idx_sh  = (int*)(smem_f + IDX_OFF);
    int*  pooled  = (int*)(smem_f + PL_OFF);
    int*  tno     = (int*)(smem_f + TNO_OFF);

    // weights: W2 pairs (m, m+4) per (c, ks*4+tig), tf32
    for (int j = tid; j < 136*17; j += 256) {
        int c = j / 17, k = j - c*17;
        float v0 = 0.f, v1 = 0.f;
        if (k < 16 && c < CIN) {
            int ks = k >> 2, tg = k & 3;
            v0 = W2[(ks*8 + tg)*CIN + c];
            v1 = W2[(ks*8 + tg + 4)*CIN + c];
        }
        W2p[j] = make_float2(to_tf32(v0), to_tf32(v1));
    }
    for (int i = tid; i < 160; i += 256) b2s[i] = (i < CIN) ? b2[i] : 0.f;
    for (int i = tid; i < 320; i += 256) W1s[i] = W1[i];
    if (tid < 32) b1s[tid] = b1[tid];
    // zero all A-frag pad rows (rows 12..15 of each warp tile) once
    for (int i = tid; i < 1024; i += 256) {
        int wq = i >> 7, r = i & 127;
        Hs[wq*512 + 384 + r] = 0.f;
    }

    for (;;) {
        if (tid == 0) *tno = atomicAdd(&g_task, 1);
        __syncthreads();
        int t = *tno;
        if (t >= NTASK) break;

        if (t < NTILES) {
            // ---- transpose tile (b-fastest) into Hs[32][33]
            float* u_buf = Hs;
            int tb  = t & 15;
            int rem = t >> 4;
            int c0  = (rem & 3) * 32, n0 = (rem >> 2) * 32;
            int tx = tid & 31, ty8 = tid >> 5;
            const float* srcf = feat + (size_t)tb * Cn * Nn;
            float* dst = g_featT + (size_t)tb * Nn * Cn;
#pragma unroll
            for (int j = 0; j < 32; j += 8)
                u_buf[(ty8 + j)*33 + tx] = srcf[(size_t)(c0 + ty8 + j) * Nn + n0 + tx];
            __syncthreads();
#pragma unroll
            for (int j = 0; j < 32; j += 8)
                dst[(size_t)(n0 + ty8 + j) * Cn + c0 + tx] = u_buf[tx*33 + ty8 + j];
            __syncthreads();
            if (tid == 0) {
                __threadfence();
                atomicAdd((int*)&g_tdone, 1);
            }
            continue;
        }

        // =============== center task (b-fastest) ===========================
        int ct = t - NTILES;
        int b = ct & 15, p = ct >> 4;
        int blk = b*NP + p;
        const float* bp = xyz + (size_t)b * Nn * 3;

        for (int i = tid; i < 396; i += 256) pooled[i] = 0;
        // re-zero pads of warps 0/1 only (tile tasks may have clobbered them)
        if (tid < 256) {
            int i = tid & 255;
            if (i < 256) {
                int off = (i < 128) ? (384 + i) : (768 + i);
                Hs[off] = 0.f;
            }
        }
        if (tid == 0) {
            while (g_prog[b] <= p || g_tdone < NTILES) __nanosleep(64);
            __threadfence();
        }
        __syncthreads();

        float cx = out_xyz[(size_t)blk*3 + 0];
        float cy = out_xyz[(size_t)blk*3 + 1];
        float cz = out_xyz[(size_t)blk*3 + 2];

        // phase A: d2 once, 3 ballots
        {
            int chunk0 = w*8;
#pragma unroll
            for (int j = 0; j < 8; ++j) {
                int i = (chunk0 + j)*32 + lane;
                float qx = bp[i*3 + 0], qy = bp[i*3 + 1], qz = bp[i*3 + 2];
                float ax = cx - qx, ay = cy - qy, az = cz - qz;
                float d2 = __fadd_rn(__fadd_rn(__fmul_rn(ax,ax), __fmul_rn(ay,ay)),
                                     __fmul_rn(az,az));
                unsigned m0 = __ballot_sync(0xffffffffu, d2 < (float)(0.1*0.1));
                unsigned m1 = __ballot_sync(0xffffffffu, d2 < (float)(0.2*0.2));
                unsigned m2 = __ballot_sync(0xffffffffu, d2 < (float)(0.4*0.4));
                if (lane == 0) {
                    masks[0*64 + chunk0 + j] = m0;
                    masks[1*64 + chunk0 + j] = m1;
                    masks[2*64 + chunk0 + j] = m2;
                }
            }
        }
        __syncthreads();

        // phase B: warps 0-2 extract first-ns ascending indices
        if (w < 3) {
            const int ns  = (w == 0) ? 16 : (w == 1) ? 32 : 48;
            const int off = (w == 0) ? 0  : (w == 1) ? 16 : 48;
            const unsigned* MM = masks + w*64;
            unsigned ma = MM[lane], mb = MM[lane + 32];
            int pa = __popc(ma), pb = __popc(mb);
            int sa = pa;
#pragma unroll
            for (int d = 1; d < 32; d <<= 1) {
                int n = __shfl_up_sync(0xffffffffu, sa, d);
                if (lane >= d) sa += n;
            }
            int totA = __shfl_sync(0xffffffffu, sa, 31);
            int sb_ = pb;
#pragma unroll
            for (int d = 1; d < 32; d <<= 1) {
                int n = __shfl_up_sync(0xffffffffu, sb_, d);
                if (lane >= d) sb_ += n;
            }
            int cnt = totA + __shfl_sync(0xffffffffu, sb_, 31);
            int pos = sa - pa;
            unsigned m = ma; int cb = lane*32;
            while (m && pos < ns) {
                int bix = __ffs(m) - 1;
                idx_sh[off + pos] = cb + bix;
                m &= m - 1; ++pos;
            }
            pos = totA + sb_ - pb;
            m = mb; cb = (lane + 32)*32;
            while (m && pos < ns) {
                int bix = __ffs(m) - 1;
                idx_sh[off + pos] = cb + bix;
                m &= m - 1; ++pos;
            }
            __syncwarp();
            if (cnt < ns) {
                int f0 = idx_sh[off];
                for (int q = cnt + lane; q < ns; q += 32) idx_sh[off + q] = f0;
            }
        }
        __syncthreads();    // masks dead; rel_s reuse OK

        // ---- W1 phase: warp w owns samples j in [w*12, w*12+12) ----
        const float* ftb = g_featT + (size_t)b * Nn * Cn;
        float* HsW = Hs + w*512;
#pragma unroll 1
        for (int q = 0; q < 12; ++q) {
            int j = w*12 + q;
            int ii = idx_sh[j];
            float gx = bp[ii*3 + 0], gy = bp[ii*3 + 1], gz = bp[ii*3 + 2];
            float rx = gx - cx, ry = gy - cy, rz = gz - cz;
            if (lane < 3)
                rel_s[j*3 + lane] = (lane == 0) ? rx : (lane == 1) ? ry : rz;
            float dn = sqrtf(rx*rx + ry*ry + rz*rz);
            float a = b1s[lane];
            a = fmaf(dn, W1s[0*32 + lane], a);
            a = fmaf(cx, W1s[1*32 + lane], a);
            a = fmaf(cy, W1s[2*32 + lane], a);
            a = fmaf(cz, W1s[3*32 + lane], a);
            a = fmaf(gx, W1s[4*32 + lane], a);
            a = fmaf(gy, W1s[5*32 + lane], a);
            a = fmaf(gz, W1s[6*32 + lane], a);
            a = fmaf(rx, W1s[7*32 + lane], a);
            a = fmaf(ry, W1s[8*32 + lane], a);
            a = fmaf(rz, W1s[9*32 + lane], a);
            HsW[q*32 + lane] = to_tf32(fmaxf(a, 0.f));
        }
        __syncwarp();

        // ---- tf32 MMA: D[12 samples][131 cols], pipelined nt loop ----
        int gid = lane >> 2, tig = lane & 3;
        const unsigned* Hsu = (const unsigned*)HsW;
        unsigned afr[4][4];
#pragma unroll
        for (int ks = 0; ks < 4; ++ks) {
            afr[ks][0] = Hsu[gid*32 + ks*8 + tig];
            afr[ks][1] = Hsu[(gid + 8)*32 + ks*8 + tig];
            afr[ks][2] = Hsu[gid*32 + ks*8 + tig + 4];
            afr[ks][3] = Hsu[(gid + 8)*32 + ks*8 + tig + 4];
        }
        int j0 = w*12 + gid;
        bool v1 = (gid < 4);
        int j1 = v1 ? (j0 + 8) : j0;
        int i0 = idx_sh[j0];
        int i1 = idx_sh[j1];
        int s0_ = (j0 < 16) ? 0 : (j0 < 48) ? 1 : 2;
        int s1_ = (j1 < 16) ? 0 : (j1 < 48) ? 1 : 2;
        bool uniformW = (w != 1);
        int sW = (w*12 < 16) ? 0 : (w*12 < 48) ? 1 : 2;

#pragma unroll 2
        for (int nt = 0; nt < 17; ++nt) {
            int c0 = nt*8 + 2*tig;
            int c1 = c0 + 1;
            bool ok0 = c0 < CIN, ok1 = c1 < CIN;
            // hoisted epilogue operand loads (issue before MMA chain)
            float x00 = ok0 ? ((c0 < 3) ? rel_s[j0*3 + c0]
                                        : ftb[(size_t)i0*Cn + c0 - 3]) : 0.f;
            float x10 = ok1 ? ((c1 < 3) ? rel_s[j0*3 + c1]
                                        : ftb[(size_t)i0*Cn + c1 - 3]) : 0.f;
            float x01 = (ok0 && v1) ? ((c0 < 3) ? rel_s[j1*3 + c0]
                                                : ftb[(size_t)i1*Cn + c0 - 3]) : 0.f;
            float x11 = (ok1 && v1) ? ((c1 < 3) ? rel_s[j1*3 + c1]
                                                : ftb[(size_t)i1*Cn + c1 - 3]) : 0.f;
            // paired B frags: 4x LDS.64
            const float2* wrow = W2p + (nt*8 + gid)*17 + tig;
            float2 B0 = wrow[0];
            float2 B1 = wrow[4];
            float2 B2 = wrow[8];
            float2 B3 = wrow[12];
            float d0 = b2s[c0], d1 = b2s[c1];
            float d2 = d0, d3 = d1;
            MMA_TF32(d0, d1, d2, d3, afr[0][0], afr[0][1], afr[0][2], afr[0][3],
                     __float_as_uint(B0.x), __float_as_uint(B0.y));
            MMA_TF32(d0, d1, d2, d3, afr[1][0], afr[1][1], afr[1][2], afr[1][3],
                     __float_as_uint(B1.x), __float_as_uint(B1.y));
            MMA_TF32(d0, d1, d2, d3, afr[2][0], afr[2][1], afr[2][2], afr[2][3],
                     __float_as_uint(B2.x), __float_as_uint(B2.y));
            MMA_TF32(d0, d1, d2, d3, afr[3][0], afr[3][1], afr[3][2], afr[3][3],
                     __float_as_uint(B3.x), __float_as_uint(B3.y));
            float va = fmaxf(d0*x00, 0.f);
            float vb = fmaxf(d1*x10, 0.f);
            float vc = v1 ? fmaxf(d2*x01, 0.f) : 0.f;
            float vd = v1 ? fmaxf(d3*x11, 0.f) : 0.f;
            if (uniformW) {
                float m0 = fmaxf(va, vc), m1 = fmaxf(vb, vd);
#pragma unroll
                for (int off = 4; off < 32; off <<= 1) {
                    m0 = fmaxf(m0, __shfl_xor_sync(0xffffffffu, m0, off));
                    m1 = fmaxf(m1, __shfl_xor_sync(0xffffffffu, m1, off));
                }
                if (gid == 0) {
                    if (ok0) atomicMax(&pooled[sW*132 + c0], __float_as_int(m0));
                    if (ok1) atomicMax(&pooled[sW*132 + c1], __float_as_int(m1));
                }
            } else {
                if (ok0) {
                    atomicMax(&pooled[s0_*132 + c0], __float_as_int(va));
                    if (v1) atomicMax(&pooled[s1_*132 + c0], __float_as_int(vc));
                }
                if (ok1) {
                    atomicMax(&pooled[s0_*132 + c1], __float_as_int(vb));
                    if (v1) atomicMax(&pooled[s1_*132 + c1], __float_as_int(vd));
                }
            }
        }
        __syncthreads();
        for (int i = tid; i < 3*CIN; i += 256) {
            int s = i / CIN, c = i - s*CIN;
            g_pooled[(size_t)(s*8192 + blk)*PROW + c] = __int_as_float(pooled[s*132 + c]);
        }
        __syncthreads();
    }
}

// ---------------------------------------------------------------------------
// K3: relu(pooled @ Wcr + bcr), 64-row tiles, acc[8][4] (measured 48.6us).
// Block 0 also resets sync state for the next graph replay.
// ---------------------------------------------------------------------------
__global__ __launch_bounds__(256) void k_proj(const float* __restrict__ Wcr,
                                              const float* __restrict__ bcr,
                                              float* __restrict__ outF) {
    if (blockIdx.x == 0 && threadIdx.x == 0) {
        g_task = 0;
        g_tdone = 0;
#pragma unroll
        for (int i = 0; i < Bn; ++i) g_prog[i] = 0;
    }
    __shared__ __align__(16) float Ps[131*68];
    __shared__ __align__(16) float Wp[32*128];
    __shared__ float bs[128];
    int tid = threadIdx.x;
    int row0 = blockIdx.x * 64;
    for (int idx = tid; idx < 64*131; idx += 256) {
        int r = idx / 131, k = idx - r*131;
        Ps[k*68 + r] = g_pooled[(size_t)(row0 + r)*PROW + k];
    }
    if (tid < 128) bs[tid] = bcr[tid];
    float acc[8][4];
#pragma unroll
    for (int r = 0; r < 8; ++r)
#pragma unroll
        for (int o = 0; o < 4; ++o) acc[r][o] = 0.f;
    int cg = tid & 31, rg = tid >> 5;
    for (int kp = 0; kp < 5; ++kp) {
        int kb = kp*32;
        int klen = (kp == 4) ? 3 : 32;
        __syncthreads();
        for (int idx = tid; idx < klen*128; idx += 256) Wp[idx] = Wcr[kb*128 + idx];
        __syncthreads();
        for (int kk = 0; kk < klen; ++kk) {
            float4 wv  = *(const float4*)&Wp[kk*128 + cg*4];
            float4 av0 = *(const float4*)&Ps[(kb + kk)*68 + rg*8];
            float4 av1 = *(const float4*)&Ps[(kb + kk)*68 + rg*8 + 4];
#pragma unroll
            for (int h = 0; h < 2; ++h) {
                float4 av = h ? av1 : av0;
                int rb = h*4;
                acc[rb+0][0] = fmaf(av.x, wv.x, acc[rb+0][0]);
                acc[rb+0][1] = fmaf(av.x, wv.y, acc[rb+0][1]);
                acc[rb+0][2] = fmaf(av.x, wv.z, acc[rb+0][2]);
                acc[rb+0][3] = fmaf(av.x, wv.w, acc[rb+0][3]);
                acc[rb+1][0] = fmaf(av.y, wv.x, acc[rb+1][0]);
                acc[rb+1][1] = fmaf(av.y, wv.y, acc[rb+1][1]);
                acc[rb+1][2] = fmaf(av.y, wv.z, acc[rb+1][2]);
                acc[rb+1][3] = fmaf(av.y, wv.w, acc[rb+1][3]);
                acc[rb+2][0] = fmaf(av.z, wv.x, acc[rb+2][0]);
                acc[rb+2][1] = fmaf(av.z, wv.y, acc[rb+2][1]);
                acc[rb+2][2] = fmaf(av.z, wv.z, acc[rb+2][2]);
                acc[rb+2][3] = fmaf(av.z, wv.w, acc[rb+2][3]);
                acc[rb+3][0] = fmaf(av.w, wv.x, acc[rb+3][0]);
                acc[rb+3][1] = fmaf(av.w, wv.y, acc[rb+3][1]);
                acc[rb+3][2] = fmaf(av.w, wv.z, acc[rb+3][2]);
                acc[rb+3][3] = fmaf(av.w, wv.w, acc[rb+3][3]);
            }
        }
    }
#pragma unroll
    for (int rr = 0; rr < 8; ++rr) {
        int row = row0 + rg*8 + rr;
        int s  = row >> 13;
        int bb = (row >> 9) & 15;
        int pp = row & 511;
        size_t obase = (size_t)bb*(384*512) + (size_t)(s*128)*512 + pp;
#pragma unroll
        for (int oo = 0; oo < 4; ++oo) {
            float v = acc[rr][oo] + bs[cg*4 + oo];
            outF[obase + (size_t)(cg*4 + oo)*512] = fmaxf(v, 0.f);
        }
    }
}

// ---------------------------------------------------------------------------
extern "C" void kernel_launch(void* const* d_in, const int* in_sizes, int n_in,
                              void* d_out, int out_size) {
    const float* xyz  = (const float*)d_in[0];
    const float* feat = (const float*)d_in[1];
    const float* W1   = (const float*)d_in[2];
    const float* b1   = (const float*)d_in[3];
    const float* W2   = (const float*)d_in[4];
    const float* b2   = (const float*)d_in[5];
    const float* Wcr  = (const float*)d_in[6];
    const float* bcr  = (const float*)d_in[7];
    float* out      = (float*)d_out;
    float* out_xyz  = out;                 // (B,512,3)
    float* outF     = out + Bn*NP*3;       // (B,384,512)

    k_main<<<16 + NWORK, 256>>>(xyz, feat, W1, b1, W2, b2, out_xyz);
    k_proj<<<384, 256>>>(Wcr, bcr, outF);
}

// round 15
// speedup vs baseline: 1.2122x; 1.2122x over previous
#include <cuda_runtime.h>
#include <cstddef>

#define Bn 16
#define Nn 2048
#define Cn 128
#define NP 512
#define CIN 131
#define PROW 132
#define NROWS (3*Bn*NP)
#define NTILES 4096
#define NCTR   8192
#define NTASK  (NTILES + NCTR)
#define NWORK  768

__device__ float g_featT[Bn*Nn*Cn];
__device__ float g_pooled[NROWS*PROW];
__device__ volatile int g_prog[Bn];        // FPS progress per batch
__device__ int g_task = 0;                 // global ticket
__device__ volatile int g_tdone = 0;       // transpose tiles completed

// smem overlay (float offsets):
//  worker: W2m[0,4096)    ([i][mb][lane][4], conflict-free float4)
//          W2t[4096,4192) ([3][32] tail rows c=128..130)
//          b2s[4192,4352) W1s[4352,4672) b1s[4672,4704)
//          u_buf[4704,5760) (tile 1056 | h1buf 1024)
//          masks[5760,5952) idx[5952,6048)
//          pooledW[6048,9216) ([8 warps][3 iters][132])
//          tno@9216
//  fps:    xs[0,2048) ys[2048,4096) zs[4096,6144) cand float4[2][8] @6144
#define W2M_OFF 0
#define W2T_OFF 4096
#define B2_OFF  4192
#define W1_OFF  4352
#define B1_OFF  4672
#define UB_OFF  4704
#define MK_OFF  5760
#define IDX_OFF 5952
#define PW_OFF  6048
#define TNO_OFF 9216
#define SMEMF   9220

__global__ __launch_bounds__(256) void k_main(const float* __restrict__ xyz,
                                              const float* __restrict__ feat,
                                              const float* __restrict__ W1,
                                              const float* __restrict__ b1,
                                              const float* __restrict__ W2,
                                              const float* __restrict__ b2,
                                              float* __restrict__ out_xyz) {
    __shared__ __align__(16) float smem_f[SMEMF];
    int tid = threadIdx.x, lane = tid & 31, w = tid >> 5;

    if (blockIdx.x < 16) {
        // ================= FPS (one block per batch, 8 pts/thread) =========
        float* xs = smem_f;
        float* ys = smem_f + 2048;
        float* zs = smem_f + 4096;
        float4* cand = (float4*)(smem_f + 6144);   // [2][8]
        int b = blockIdx.x;
        const float* src = xyz + (size_t)b * Nn * 3;
        for (int t = tid; t < Nn; t += 256) {
            xs[t] = src[t*3 + 0]; ys[t] = src[t*3 + 1]; zs[t] = src[t*3 + 2];
        }
        __syncthreads();
        float X[8], Y[8], Z[8], D[8];
#pragma unroll
        for (int q = 0; q < 8; ++q) {
            int i = tid*8 + q;
            X[q] = xs[i]; Y[q] = ys[i]; Z[q] = zs[i];
            D[q] = 1e10f;
        }
        float px = xs[0], py = ys[0], pz = zs[0];
        if (tid == 0) {
            out_xyz[(size_t)b*NP*3 + 0] = px;
            out_xyz[(size_t)b*NP*3 + 1] = py;
            out_xyz[(size_t)b*NP*3 + 2] = pz;
        }
        for (int it = 1; it < NP; ++it) {
#pragma unroll
            for (int q = 0; q < 8; ++q) {
                float ax = X[q] - px, ay = Y[q] - py, az = Z[q] - pz;
                float dd = __fadd_rn(__fadd_rn(__fmul_rn(ax,ax), __fmul_rn(ay,ay)),
                                     __fmul_rn(az,az));
                D[q] = fminf(D[q], dd);
            }
            float v0 = D[0], xa = X[0], ya = Y[0], za = Z[0];
            if (D[1] > v0) { v0 = D[1]; xa = X[1]; ya = Y[1]; za = Z[1]; }
            float v2 = D[2], xb = X[2], yb = Y[2], zb = Z[2];
            if (D[3] > v2) { v2 = D[3]; xb = X[3]; yb = Y[3]; zb = Z[3]; }
            float v4 = D[4], xc = X[4], yc = Y[4], zc = Z[4];
            if (D[5] > v4) { v4 = D[5]; xc = X[5]; yc = Y[5]; zc = Z[5]; }
            float v6 = D[6], xd = X[6], yd = Y[6], zd = Z[6];
            if (D[7] > v6) { v6 = D[7]; xd = X[7]; yd = Y[7]; zd = Z[7]; }
            if (v2 > v0) { v0 = v2; xa = xb; ya = yb; za = zb; }
            if (v6 > v4) { v4 = v6; xc = xd; yc = yd; zc = zd; }
            if (v4 > v0) { v0 = v4; xa = xc; ya = yc; za = zc; }
            unsigned bits = __float_as_uint(v0);
            unsigned m = __reduce_max_sync(0xffffffffu, bits);
            unsigned bal = __ballot_sync(0xffffffffu, bits == m);
            int srcl = __ffs(bal) - 1;
            float wx = __shfl_sync(0xffffffffu, xa, srcl);
            float wy = __shfl_sync(0xffffffffu, ya, srcl);
            float wz = __shfl_sync(0xffffffffu, za, srcl);
            int bufi = it & 1;
            if (lane == 0)
                cand[bufi*8 + w] = make_float4(__uint_as_float(m), wx, wy, wz);
            __syncthreads();
            float4 c = cand[bufi*8 + (lane & 7)];
            unsigned vv = __float_as_uint(c.x);
            unsigned m2 = __reduce_max_sync(0xffffffffu, vv);
            unsigned b2_ = __ballot_sync(0xffffffffu, vv == m2);
            int s2 = __ffs(b2_) - 1;
            px = __shfl_sync(0xffffffffu, c.y, s2);
            py = __shfl_sync(0xffffffffu, c.z, s2);
            pz = __shfl_sync(0xffffffffu, c.w, s2);
            if (tid == 0) {
                out_xyz[(size_t)(b*NP + it)*3 + 0] = px;
                out_xyz[(size_t)(b*NP + it)*3 + 1] = py;
                out_xyz[(size_t)(b*NP + it)*3 + 2] = pz;
                if ((it & 3) == 3 || it == NP-1) {
                    __threadfence();
                    g_prog[b] = it + 1;
                }
            }
        }
        return;
    }

    // ================= persistent worker ===================================
    float* W2m    = smem_f + W2M_OFF;   // [i][mb][lane][4]
    float* W2t    = smem_f + W2T_OFF;   // [3][32]
    float* b2s    = smem_f + B2_OFF;
    float* W1s    = smem_f + W1_OFF;
    float* b1s    = smem_f + B1_OFF;
    float* u_buf  = smem_f + UB_OFF;
    unsigned* masks = (unsigned*)(smem_f + MK_OFF);
    int*  idx_sh  = (int*)(smem_f + IDX_OFF);
    float* pooledW = smem_f + PW_OFF;   // [8][3][132]
    int*  tno     = (int*)(smem_f + TNO_OFF);

    // weights: W2m conflict-free layout; W2t tail rows
    for (int j = tid; j < 4096; j += 256) {
        int k = j & 3, ln = (j >> 2) & 31, mb = (j >> 7) & 7, i = j >> 10;
        W2m[j] = W2[(mb*4 + k)*CIN + i*32 + ln];
    }
    for (int j = tid; j < 96; j += 256) {
        int cc = j >> 5, m = j & 31;
        W2t[j] = W2[m*CIN + 128 + cc];
    }
    for (int i = tid; i < 160; i += 256) b2s[i] = (i < CIN) ? b2[i] : 0.f;
    for (int i = tid; i < 320; i += 256) W1s[i] = W1[i];
    if (tid < 32) b1s[tid] = b1[tid];

    for (;;) {
        if (tid == 0) *tno = atomicAdd(&g_task, 1);
        __syncthreads();
        int t = *tno;
        if (t >= NTASK) break;

        if (t < NTILES) {
            // ---- transpose tile (b-fastest) into u_buf[32][33]
            int tb  = t & 15;
            int rem = t >> 4;
            int c0  = (rem & 3) * 32, n0 = (rem >> 2) * 32;
            int tx = tid & 31, ty8 = tid >> 5;
            const float* srcf = feat + (size_t)tb * Cn * Nn;
            float* dst = g_featT + (size_t)tb * Nn * Cn;
#pragma unroll
            for (int j = 0; j < 32; j += 8)
                u_buf[(ty8 + j)*33 + tx] = srcf[(size_t)(c0 + ty8 + j) * Nn + n0 + tx];
            __syncthreads();
#pragma unroll
            for (int j = 0; j < 32; j += 8)
                dst[(size_t)(n0 + ty8 + j) * Cn + c0 + tx] = u_buf[tx*33 + ty8 + j];
            __syncthreads();
            if (tid == 0) {
                __threadfence();
                atomicAdd((int*)&g_tdone, 1);
            }
            continue;
        }

        // =============== center task (b-fastest) ===========================
        int ct = t - NTILES;
        int b = ct & 15, p = ct >> 4;
        int blk = b*NP + p;
        const float* bp = xyz + (size_t)b * Nn * 3;

        if (tid == 0) {
            while (g_prog[b] <= p || g_tdone < NTILES) __nanosleep(64);
            __threadfence();
        }
        __syncthreads();

        float cx = out_xyz[(size_t)blk*3 + 0];
        float cy = out_xyz[(size_t)blk*3 + 1];
        float cz = out_xyz[(size_t)blk*3 + 2];

        // phase A: d2 once, 3 ballots
        {
            int chunk0 = w*8;
#pragma unroll
            for (int j = 0; j < 8; ++j) {
                int i = (chunk0 + j)*32 + lane;
                float qx = bp[i*3 + 0], qy = bp[i*3 + 1], qz = bp[i*3 + 2];
                float ax = cx - qx, ay = cy - qy, az = cz - qz;
                float d2 = __fadd_rn(__fadd_rn(__fmul_rn(ax,ax), __fmul_rn(ay,ay)),
                                     __fmul_rn(az,az));
                unsigned m0 = __ballot_sync(0xffffffffu, d2 < (float)(0.1*0.1));
                unsigned m1 = __ballot_sync(0xffffffffu, d2 < (float)(0.2*0.2));
                unsigned m2 = __ballot_sync(0xffffffffu, d2 < (float)(0.4*0.4));
                if (lane == 0) {
                    masks[0*64 + chunk0 + j] = m0;
                    masks[1*64 + chunk0 + j] = m1;
                    masks[2*64 + chunk0 + j] = m2;
                }
            }
        }
        __syncthreads();

        // phase B: warps 0-2 extract first-ns ascending indices
        if (w < 3) {
            const int ns  = (w == 0) ? 16 : (w == 1) ? 32 : 48;
            const int off = (w == 0) ? 0  : (w == 1) ? 16 : 48;
            const unsigned* MM = masks + w*64;
            unsigned ma = MM[lane], mb = MM[lane + 32];
            int pa = __popc(ma), pb = __popc(mb);
            int sa = pa;
#pragma unroll
            for (int d = 1; d < 32; d <<= 1) {
                int n = __shfl_up_sync(0xffffffffu, sa, d);
                if (lane >= d) sa += n;
            }
            int totA = __shfl_sync(0xffffffffu, sa, 31);
            int sb_ = pb;
#pragma unroll
            for (int d = 1; d < 32; d <<= 1) {
                int n = __shfl_up_sync(0xffffffffu, sb_, d);
                if (lane >= d) sb_ += n;
            }
            int cnt = totA + __shfl_sync(0xffffffffu, sb_, 31);
            int pos = sa - pa;
            unsigned m = ma; int cb = lane*32;
            while (m && pos < ns) {
                int bix = __ffs(m) - 1;
                idx_sh[off + pos] = cb + bix;
                m &= m - 1; ++pos;
            }
            pos = totA + sb_ - pb;
            m = mb; cb = (lane + 32)*32;
            while (m && pos < ns) {
                int bix = __ffs(m) - 1;
                idx_sh[off + pos] = cb + bix;
                m &= m - 1; ++pos;
            }
            __syncwarp();
            if (cnt < ns) {
                int f0 = idx_sh[off];
                for (int q = cnt + lane; q < ns; q += 32) idx_sh[off + q] = f0;
            }
        }
        __syncthreads();

        // MLP + pooling: 24 groups of 4 samples over 8 warps, iter it=0..2
        float* h1buf = u_buf;
        const float* ftb = g_featT + (size_t)b * Nn * Cn;
#pragma unroll
        for (int it = 0; it < 3; ++it) {
            int g = w + it*8;
            int s, sb, j0;
            if (g < 4)       { s = 0; sb = 0;  j0 = g * 4; }
            else if (g < 12) { s = 1; sb = 16; j0 = (g - 4) * 4; }
            else             { s = 2; sb = 48; j0 = (g - 12) * 4; }
            (void)s;
            int sidx[4]; float relx[4], rely[4], relz[4], h1v[4];
#pragma unroll
            for (int q = 0; q < 4; ++q) {
                int ii = idx_sh[sb + j0 + q];
                sidx[q] = ii;
                float gx = bp[ii*3 + 0], gy = bp[ii*3 + 1], gz = bp[ii*3 + 2];
                float rx = gx - cx, ry = gy - cy, rz = gz - cz;
                relx[q] = rx; rely[q] = ry; relz[q] = rz;
                float dn = sqrtf(rx*rx + ry*ry + rz*rz);
                float a = b1s[lane];
                a = fmaf(dn, W1s[0*32 + lane], a);
                a = fmaf(cx, W1s[1*32 + lane], a);
                a = fmaf(cy, W1s[2*32 + lane], a);
                a = fmaf(cz, W1s[3*32 + lane], a);
                a = fmaf(gx, W1s[4*32 + lane], a);
                a = fmaf(gy, W1s[5*32 + lane], a);
                a = fmaf(gz, W1s[6*32 + lane], a);
                a = fmaf(rx, W1s[7*32 + lane], a);
                a = fmaf(ry, W1s[8*32 + lane], a);
                a = fmaf(rz, W1s[9*32 + lane], a);
                h1v[q] = fmaxf(a, 0.f);
            }
            __syncwarp();
            *(float4*)&h1buf[(w*32 + lane)*4] = make_float4(h1v[0], h1v[1], h1v[2], h1v[3]);
            __syncwarp();

            // main cols 0..127: conflict-free W reads
            float acc[4][4];
#pragma unroll
            for (int i = 0; i < 4; ++i) {
                float bb = b2s[i*32 + lane];
                acc[i][0] = bb; acc[i][1] = bb; acc[i][2] = bb; acc[i][3] = bb;
            }
#pragma unroll
            for (int mb = 0; mb < 8; ++mb) {
                const float* hb = &h1buf[(w*32 + mb*4)*4];
                float4 H0 = *(const float4*)(hb + 0);
                float4 H1 = *(const float4*)(hb + 4);
                float4 H2 = *(const float4*)(hb + 8);
                float4 H3 = *(const float4*)(hb + 12);
#pragma unroll
                for (int i = 0; i < 4; ++i) {
                    float4 wv = *(const float4*)&W2m[((i*8 + mb)*32 + lane)*4];
                    acc[i][0] = fmaf(wv.x, H0.x, acc[i][0]);
                    acc[i][0] = fmaf(wv.y, H1.x, acc[i][0]);
                    acc[i][0] = fmaf(wv.z, H2.x, acc[i][0]);
                    acc[i][0] = fmaf(wv.w, H3.x, acc[i][0]);
                    acc[i][1] = fmaf(wv.x, H0.y, acc[i][1]);
                    acc[i][1] = fmaf(wv.y, H1.y, acc[i][1]);
                    acc[i][1] = fmaf(wv.z, H2.y, acc[i][1]);
                    acc[i][1] = fmaf(wv.w, H3.y, acc[i][1]);
                    acc[i][2] = fmaf(wv.x, H0.z, acc[i][2]);
                    acc[i][2] = fmaf(wv.y, H1.z, acc[i][2]);
                    acc[i][2] = fmaf(wv.z, H2.z, acc[i][2]);
                    acc[i][2] = fmaf(wv.w, H3.z, acc[i][2]);
                    acc[i][3] = fmaf(wv.x, H0.w, acc[i][3]);
                    acc[i][3] = fmaf(wv.y, H1.w, acc[i][3]);
                    acc[i][3] = fmaf(wv.z, H2.w, acc[i][3]);
                    acc[i][3] = fmaf(wv.w, H3.w, acc[i][3]);
                }
            }

            // epilogue: relu(h*x) max -> plain store to per-(warp,iter) slice
            float* PW = pooledW + (w*3 + it)*132;
#pragma unroll
            for (int i = 0; i < 4; ++i) {
                int c = i*32 + lane;
                float vmax = 0.f;
#pragma unroll
                for (int q = 0; q < 4; ++q) {
                    float xv;
                    if (i == 0) {
                        xv = (c >= 3) ? ftb[(size_t)sidx[q]*Cn + (c - 3)]
                                      : ((c == 0) ? relx[q] : (c == 1) ? rely[q] : relz[q]);
                    } else {
                        xv = ftb[(size_t)sidx[q]*Cn + (c - 3)];
                    }
                    float v = acc[i][q] * xv;
                    vmax = fmaxf(vmax, fmaxf(v, 0.f));
                }
                PW[c] = vmax;
            }

            // tail cols 128..130: 12 lanes compute, shfl-max over qq, store
            {
                float vt = 0.f;
                if (lane < 12) {
                    int qq = lane & 3, cc = lane >> 2;
                    float acct = b2s[128 + cc];
                    const float* wr = &W2t[cc*32];
#pragma unroll 8
                    for (int m = 0; m < 32; ++m)
                        acct = fmaf(wr[m], h1buf[(w*32 + m)*4 + qq], acct);
                    float xv = ftb[(size_t)sidx[qq]*Cn + 125 + cc];
                    vt = fmaxf(acct * xv, 0.f);
                }
                vt = fmaxf(vt, __shfl_xor_sync(0xffffffffu, vt, 1));
                vt = fmaxf(vt, __shfl_xor_sync(0xffffffffu, vt, 2));
                if (lane < 12 && (lane & 3) == 0)
                    PW[128 + (lane >> 2)] = vt;
            }
        }
        __syncthreads();

        // final merge: static (warp,iter)->scale map
        //  s0: (w<4, it0) | s1: (w>=4, it0)+(w<4, it1) | s2: the rest
        for (int o = tid; o < 3*CIN; o += 256) {
            int s = o / CIN, c = o - s*CIN;
            float v = 0.f;
            if (s == 0) {
#pragma unroll
                for (int ww = 0; ww < 4; ++ww)
                    v = fmaxf(v, pooledW[(ww*3 + 0)*132 + c]);
            } else if (s == 1) {
#pragma unroll
                for (int ww = 4; ww < 8; ++ww)
                    v = fmaxf(v, pooledW[(ww*3 + 0)*132 + c]);
#pragma unroll
                for (int ww = 0; ww < 4; ++ww)
                    v = fmaxf(v, pooledW[(ww*3 + 1)*132 + c]);
            } else {
#pragma unroll
                for (int ww = 4; ww < 8; ++ww)
                    v = fmaxf(v, pooledW[(ww*3 + 1)*132 + c]);
#pragma unroll
                for (int ww = 0; ww < 8; ++ww)
                    v = fmaxf(v, pooledW[(ww*3 + 2)*132 + c]);
            }
            g_pooled[(size_t)(s*8192 + blk)*PROW + c] = v;
        }
        __syncthreads();
    }
}

// ---------------------------------------------------------------------------
// K3: relu(pooled @ Wcr + bcr), 64-row tiles, acc[8][4] (measured 48.6us).
// Block 0 also resets sync state for the next graph replay.
// ---------------------------------------------------------------------------
__global__ __launch_bounds__(256) void k_proj(const float* __restrict__ Wcr,
                                              const float* __restrict__ bcr,
                                              float* __restrict__ outF) {
    if (blockIdx.x == 0 && threadIdx.x == 0) {
        g_task = 0;
        g_tdone = 0;
#pragma unroll
        for (int i = 0; i < Bn; ++i) g_prog[i] = 0;
    }
    __shared__ __align__(16) float Ps[131*68];
    __shared__ __align__(16) float Wp[32*128];
    __shared__ float bs[128];
    int tid = threadIdx.x;
    int row0 = blockIdx.x * 64;
    for (int idx = tid; idx < 64*131; idx += 256) {
        int r = idx / 131, k = idx - r*131;
        Ps[k*68 + r] = g_pooled[(size_t)(row0 + r)*PROW + k];
    }
    if (tid < 128) bs[tid] = bcr[tid];
    float acc[8][4];
#pragma unroll
    for (int r = 0; r < 8; ++r)
#pragma unroll
        for (int o = 0; o < 4; ++o) acc[r][o] = 0.f;
    int cg = tid & 31, rg = tid >> 5;
    for (int kp = 0; kp < 5; ++kp) {
        int kb = kp*32;
        int klen = (kp == 4) ? 3 : 32;
        __syncthreads();
        for (int idx = tid; idx < klen*128; idx += 256) Wp[idx] = Wcr[kb*128 + idx];
        __syncthreads();
        for (int kk = 0; kk < klen; ++kk) {
            float4 wv  = *(const float4*)&Wp[kk*128 + cg*4];
            float4 av0 = *(const float4*)&Ps[(kb + kk)*68 + rg*8];
            float4 av1 = *(const float4*)&Ps[(kb + kk)*68 + rg*8 + 4];
#pragma unroll
            for (int h = 0; h < 2; ++h) {
                float4 av = h ? av1 : av0;
                int rb = h*4;
                acc[rb+0][0] = fmaf(av.x, wv.x, acc[rb+0][0]);
                acc[rb+0][1] = fmaf(av.x, wv.y, acc[rb+0][1]);
                acc[rb+0][2] = fmaf(av.x, wv.z, acc[rb+0][2]);
                acc[rb+0][3] = fmaf(av.x, wv.w, acc[rb+0][3]);
                acc[rb+1][0] = fmaf(av.y, wv.x, acc[rb+1][0]);
                acc[rb+1][1] = fmaf(av.y, wv.y, acc[rb+1][1]);
                acc[rb+1][2] = fmaf(av.y, wv.z, acc[rb+1][2]);
                acc[rb+1][3] = fmaf(av.y, wv.w, acc[rb+1][3]);
                acc[rb+2][0] = fmaf(av.z, wv.x, acc[rb+2][0]);
                acc[rb+2][1] = fmaf(av.z, wv.y, acc[rb+2][1]);
                acc[rb+2][2] = fmaf(av.z, wv.z, acc[rb+2][2]);
                acc[rb+2][3] = fmaf(av.z, wv.w, acc[rb+2][3]);
                acc[rb+3][0] = fmaf(av.w, wv.x, acc[rb+3][0]);
                acc[rb+3][1] = fmaf(av.w, wv.y, acc[rb+3][1]);
                acc[rb+3][2] = fmaf(av.w, wv.z, acc[rb+3][2]);
                acc[rb+3][3] = fmaf(av.w, wv.w, acc[rb+3][3]);
            }
        }
    }
#pragma unroll
    for (int rr = 0; rr < 8; ++rr) {
        int row = row0 + rg*8 + rr;
        int s  = row >> 13;
        int bb = (row >> 9) & 15;
        int pp = row & 511;
        size_t obase = (size_t)bb*(384*512) + (size_t)(s*128)*512 + pp;
#pragma unroll
        for (int oo = 0; oo < 4; ++oo) {
            float v = acc[rr][oo] + bs[cg*4 + oo];
            outF[obase + (size_t)(cg*4 + oo)*512] = fmaxf(v, 0.f);
        }
    }
}

// ---------------------------------------------------------------------------
extern "C" void kernel_launch(void* const* d_in, const int* in_sizes, int n_in,
                              void* d_out, int out_size) {
    const float* xyz  = (const float*)d_in[0];
    const float* feat = (const float*)d_in[1];
    const float* W1   = (const float*)d_in[2];
    const float* b1   = (const float*)d_in[3];
    const float* W2   = (const float*)d_in[4];
    const float* b2   = (const float*)d_in[5];
    const float* Wcr  = (const float*)d_in[6];
    const float* bcr  = (const float*)d_in[7];
    float* out      = (float*)d_out;
    float* out_xyz  = out;                 // (B,512,3)
    float* outF     = out + Bn*NP*3;       // (B,384,512)

    k_main<<<16 + NWORK, 256>>>(xyz, feat, W1, b1, W2, b2, out_xyz);
    k_proj<<<384, 256>>>(Wcr, bcr, outF);
}